// round 8
// baseline (speedup 1.0000x reference)
#include <cuda_runtime.h>

// UnPooling (max-unpool 2x2): x [16,128,128,256] f32, pooled [16,64,64,256] f32
// out [16,128,128,256] f32: max(pooled,0) at argmax slot of each 2x2 window, else 0.
//
// NHWC, hardcoded: N=16, H=128, W=128, C=256, Hp=64, Wp=64.
// FINAL — converged at the HBM roofline (R1-R7 sweep):
//   flat launch, 128-bit accesses, 28 regs, block 512
//   kernel 82.4-83.3us, 6.63-6.68 TB/s (83-84% of 8TB/s spec), DRAM busy ~84%
// Ruled out by measurement: streaming hints (neutral), 256-bit accesses
// (occupancy loss), persistent grid (MLP/page-locality loss), block-size
// changes (neutral). Ruled out analytically: sparse scatter (write-allocate
// RMW), TMA path (LTS cap is path-independent on B300).
// CV = C/4 = 64 float4 per pixel; x row stride 8192, col stride 64 (float4 units).

__global__ __launch_bounds__(512) void unpool_kernel(const float4* __restrict__ x,
                                                     const float4* __restrict__ pooled,
                                                     float4* __restrict__ out,
                                                     int total)
{
    int tid = blockIdx.x * blockDim.x + threadIdx.x;
    if (tid >= total) return;

    // tid linear over pooled in float4 units: ((n*Hp+hp)*Wp+wp)*CV + cv
    int cv = tid & 63;          // CV = 64
    int wp = (tid >> 6) & 63;   // Wp = 64
    int hp = (tid >> 12) & 63;  // Hp = 64
    int n  = tid >> 18;

    // base float4 index into x/out at (n, 2*hp, 2*wp, cv)
    int b = ((n * 128 + 2 * hp) * 128 + 2 * wp) * 64 + cv;

    float4 v00 = x[b];
    float4 v01 = x[b + 64];      // (dh=0, dw=1)
    float4 v10 = x[b + 8192];    // (dh=1, dw=0)
    float4 v11 = x[b + 8256];    // (dh=1, dw=1)
    float4 p   = pooled[tid];

    float4 o00, o01, o10, o11;

    // Row-major (dh,dw) order, first-max tie-break => strict '>' for later slots.
#define UNPOOL_COMP(F)                                                \
    {                                                                 \
        float t0 = v00.F, t1 = v01.F, t2 = v10.F, t3 = v11.F;         \
        int   idx = 0;                                                \
        float best = t0;                                              \
        if (t1 > best) { best = t1; idx = 1; }                        \
        if (t2 > best) { best = t2; idx = 2; }                        \
        if (t3 > best) { best = t3; idx = 3; }                        \
        float pv = fmaxf(p.F, 0.0f);                                  \
        o00.F = (idx == 0) ? pv : 0.0f;                               \
        o01.F = (idx == 1) ? pv : 0.0f;                               \
        o10.F = (idx == 2) ? pv : 0.0f;                               \
        o11.F = (idx == 3) ? pv : 0.0f;                               \
    }

    UNPOOL_COMP(x)
    UNPOOL_COMP(y)
    UNPOOL_COMP(z)
    UNPOOL_COMP(w)
#undef UNPOOL_COMP

    out[b]        = o00;
    out[b + 64]   = o01;
    out[b + 8192] = o10;
    out[b + 8256] = o11;
}

extern "C" void kernel_launch(void* const* d_in, const int* in_sizes, int n_in,
                              void* d_out, int out_size)
{
    const float4* x      = (const float4*)d_in[0];
    const float4* pooled = (const float4*)d_in[1];
    float4*       out    = (float4*)d_out;

    const int total = 16 * 64 * 64 * 64;   // pooled float4 count = 4,194,304
    const int threads = 512;
    const int blocks  = (total + threads - 1) / threads;
    unpool_kernel<<<blocks, threads>>>(x, pooled, out, total);
}

// round 9
// speedup vs baseline: 1.0085x; 1.0085x over previous
#include <cuda_runtime.h>

// UnPooling (max-unpool 2x2): x [16,128,128,256] f32, pooled [16,64,64,256] f32
// out [16,128,128,256] f32: max(pooled,0) at argmax slot of each 2x2 window, else 0.
//
// NHWC, hardcoded: N=16, H=128, W=128, C=256, Hp=64, Wp=64.
// FINAL — converged at the HBM roofline (verified over 5 identical-config runs,
// R1/R4/R6/R7/R8: kernel 82.4-83.8us, 6.58-6.68 TB/s, DRAM busy 83-84%).
// 604 MB irreducible traffic / achievable R+W bandwidth == measured time.
// Ruled out by measurement: streaming hints (neutral), 256-bit accesses
// (occupancy loss, -3%), persistent grid (MLP/page-locality loss, -7%),
// block-size changes (neutral). Ruled out analytically: sparse scatter
// (write-allocate RMW adds reads), TMA (LTS cap path-independent on B300).
// CV = C/4 = 64 float4 per pixel; x row stride 8192, col stride 64 (float4 units).

__global__ __launch_bounds__(512) void unpool_kernel(const float4* __restrict__ x,
                                                     const float4* __restrict__ pooled,
                                                     float4* __restrict__ out,
                                                     int total)
{
    int tid = blockIdx.x * blockDim.x + threadIdx.x;
    if (tid >= total) return;

    // tid linear over pooled in float4 units: ((n*Hp+hp)*Wp+wp)*CV + cv
    int cv = tid & 63;          // CV = 64
    int wp = (tid >> 6) & 63;   // Wp = 64
    int hp = (tid >> 12) & 63;  // Hp = 64
    int n  = tid >> 18;

    // base float4 index into x/out at (n, 2*hp, 2*wp, cv)
    int b = ((n * 128 + 2 * hp) * 128 + 2 * wp) * 64 + cv;

    float4 v00 = x[b];
    float4 v01 = x[b + 64];      // (dh=0, dw=1)
    float4 v10 = x[b + 8192];    // (dh=1, dw=0)
    float4 v11 = x[b + 8256];    // (dh=1, dw=1)
    float4 p   = pooled[tid];

    float4 o00, o01, o10, o11;

    // Row-major (dh,dw) order, first-max tie-break => strict '>' for later slots.
#define UNPOOL_COMP(F)                                                \
    {                                                                 \
        float t0 = v00.F, t1 = v01.F, t2 = v10.F, t3 = v11.F;         \
        int   idx = 0;                                                \
        float best = t0;                                              \
        if (t1 > best) { best = t1; idx = 1; }                        \
        if (t2 > best) { best = t2; idx = 2; }                        \
        if (t3 > best) { best = t3; idx = 3; }                        \
        float pv = fmaxf(p.F, 0.0f);                                  \
        o00.F = (idx == 0) ? pv : 0.0f;                               \
        o01.F = (idx == 1) ? pv : 0.0f;                               \
        o10.F = (idx == 2) ? pv : 0.0f;                               \
        o11.F = (idx == 3) ? pv : 0.0f;                               \
    }

    UNPOOL_COMP(x)
    UNPOOL_COMP(y)
    UNPOOL_COMP(z)
    UNPOOL_COMP(w)
#undef UNPOOL_COMP

    out[b]        = o00;
    out[b + 64]   = o01;
    out[b + 8192] = o10;
    out[b + 8256] = o11;
}

extern "C" void kernel_launch(void* const* d_in, const int* in_sizes, int n_in,
                              void* d_out, int out_size)
{
    const float4* x      = (const float4*)d_in[0];
    const float4* pooled = (const float4*)d_in[1];
    float4*       out    = (float4*)d_out;

    const int total = 16 * 64 * 64 * 64;   // pooled float4 count = 4,194,304
    const int threads = 512;
    const int blocks  = (total + threads - 1) / threads;
    unpool_kernel<<<blocks, threads>>>(x, pooled, out, total);
}